// round 15
// baseline (speedup 1.0000x reference)
#include <cuda_runtime.h>
#include <cuda_fp16.h>

#define NN   100000
#define EE   1600000
#define TW   12
#define CI_N 16
#define CMID 32
#define COUT 32

#define NSCAN 98                      // ceil(NN/1024)

// ---- scratch (allocation-free rule: __device__ globals) ----
struct ZBlob {                         // zeroed by ONE memset per launch
    unsigned long long pk[NN];         // (cnt << 32) | fixed-point(deg, 2^-24)
    unsigned long long stat[NSCAN];    // decoupled-lookback state
};
__device__ ZBlob   g_zb;
__device__ float   g_dis[NN];
__device__ int     g_off[NN + 1];
__device__ int     g_cur[NN];
__device__ float2  g_edge[EE];                        // (src as int bits, ew*dis[dst])
__device__ __half  g_xsh[(size_t)NN * TW * CI_N];     // dis[n]*x, node-major fp16
__device__ __half2 g_axh[(size_t)NN * 96];            // aggregated x, fp16 (38.4 MB)
__device__ float   g_M  [TW * 3 * CI_N * COUT];       // fused gcn_w @ conv_w
__device__ float   g_B  [TW * COUT];                  // fused bias

// ---- packed f32x2 helpers (Blackwell FFMA2) ----
__device__ __forceinline__ unsigned long long pk2(float lo, float hi) {
    unsigned long long r;
    asm("mov.b64 %0, {%1, %2};" : "=l"(r) : "f"(lo), "f"(hi));
    return r;
}
__device__ __forceinline__ void upk2(float& lo, float& hi, unsigned long long v) {
    asm("mov.b64 {%0, %1}, %2;" : "=f"(lo), "=f"(hi) : "l"(v));
}
__device__ __forceinline__ unsigned long long fma2(unsigned long long a,
                                                   unsigned long long b,
                                                   unsigned long long c) {
    unsigned long long d;
    asm("fma.rn.f32x2 %0, %1, %2, %3;" : "=l"(d) : "l"(a), "l"(b), "l"(c));
    return d;
}

// ================= K1: edge histogram — ONE packed 64-bit RED per edge ================
__global__ void k_megaE(const int* __restrict__ A, const float* __restrict__ ew) {
    int e2 = (blockIdx.x * 256 + threadIdx.x) * 2;     // 3125*256*2 == EE exactly
    int2   c2 = *(const int2*)(A + EE + e2);
    float2 w2 = *(const float2*)(ew + e2);
    unsigned long long p0 = (1ull << 32) | (unsigned)__float2uint_rn(w2.x * 16777216.f);
    unsigned long long p1 = (1ull << 32) | (unsigned)__float2uint_rn(w2.y * 16777216.f);
    atomicAdd(&g_zb.pk[c2.x], p0);
    atomicAdd(&g_zb.pk[c2.y], p1);
}

// ================= K2: single-pass exclusive scan + dis = rsqrt(deg) ==================
__global__ __launch_bounds__(1024) void k_scan() {
    __shared__ int wsum[33];
    __shared__ int s_prefix;
    const int tid = threadIdx.x, lane = tid & 31, wid = tid >> 5, bid = blockIdx.x;
    const int i = bid * 1024 + tid;
    unsigned long long pki = (i < NN) ? g_zb.pk[i] : 0ull;
    int v = (int)(pki >> 32);
    int incl = v;
    #pragma unroll
    for (int d = 1; d < 32; d <<= 1) {
        int t = __shfl_up_sync(0xffffffffu, incl, d);
        if (lane >= d) incl += t;
    }
    if (lane == 31) wsum[wid] = incl;
    __syncthreads();
    if (wid == 0) {
        int x  = wsum[lane];
        int ix = x;
        #pragma unroll
        for (int d = 1; d < 32; d <<= 1) {
            int t = __shfl_up_sync(0xffffffffu, ix, d);
            if (lane >= d) ix += t;
        }
        wsum[lane] = ix - x;
        if (lane == 31) wsum[32] = ix;
    }
    __syncthreads();
    const int excl  = wsum[wid] + incl - v;
    const int total = wsum[32];

    if (tid == 0) {
        unsigned long long pk = ((unsigned long long)(bid == 0 ? 2u : 1u) << 32)
                              | (unsigned)total;
        atomicExch(&g_zb.stat[bid], pk);
        if (bid == 0) s_prefix = 0;
    }
    if (bid != 0 && wid == 0) {
        volatile unsigned long long* vs = g_zb.stat;
        int pred = bid - 1;
        int run = 0;
        for (;;) {
            int idx = pred - lane;
            unsigned long long st;
            if (idx >= 0) {
                do { st = vs[idx]; } while ((unsigned)(st >> 32) == 0u);
            } else {
                st = (2ull << 32);
            }
            unsigned flag = (unsigned)(st >> 32);
            int      val  = (int)(unsigned)st;
            unsigned mask = __ballot_sync(0xffffffffu, flag == 2u);
            if (mask) {
                int L = __ffs(mask) - 1;
                int contrib = (lane <= L) ? val : 0;
                #pragma unroll
                for (int d = 16; d >= 1; d >>= 1)
                    contrib += __shfl_xor_sync(0xffffffffu, contrib, d);
                run += contrib;
                break;
            } else {
                int contrib = val;
                #pragma unroll
                for (int d = 16; d >= 1; d >>= 1)
                    contrib += __shfl_xor_sync(0xffffffffu, contrib, d);
                run += contrib;
                pred -= 32;
            }
        }
        if (lane == 0) {
            s_prefix = run;
            atomicExch(&g_zb.stat[bid], (2ull << 32) | (unsigned)(run + total));
        }
    }
    __syncthreads();
    const int pre = s_prefix;
    if (i < NN) {
        int o = excl + pre;
        g_off[i] = o;
        g_cur[i] = o;
        float deg = (float)(unsigned)(pki & 0xffffffffull) * (1.f / 16777216.f);
        g_dis[i] = deg > 0.f ? rsqrtf(deg) : 0.f;
    }
    if (bid == NSCAN - 1 && tid == 0) g_off[NN] = EE;
}

// ================= K3: scatter + node-major transpose (block-range dispatch) ==========
#define NB_S 3125                      // 3125*256*2 == EE
#define NB_T 391                       // ceil(NN/256)
__global__ void k_scatX(const int* __restrict__ A, const float* __restrict__ ew,
                        const float* __restrict__ x) {
    const int b = blockIdx.x, tid = threadIdx.x;
    if (b < NB_S) {
        int e2 = (b * 256 + tid) * 2;
        int2   r2 = *(const int2*)(A + e2);
        int2   c2 = *(const int2*)(A + EE + e2);
        float2 w2 = *(const float2*)(ew + e2);
        float n0 = w2.x * g_dis[c2.x];
        float n1 = w2.y * g_dis[c2.y];
        int i0 = atomicAdd(&g_cur[c2.x], 1);
        g_edge[i0] = make_float2(__int_as_float(r2.x), n0);
        int i1 = atomicAdd(&g_cur[c2.y], 1);
        g_edge[i1] = make_float2(__int_as_float(r2.y), n1);
    } else {
        // node-major transpose: thread = node; 12 independent read streams,
        // contiguous 384B write per node (warp: 12KB contiguous).
        int n = (b - NB_S) * 256 + tid;
        if (n < NN) {
            float ds = g_dis[n];
            uint4* dst = (uint4*)(g_xsh + (size_t)n * 192);
            #pragma unroll
            for (int tc = 0; tc < 4; tc++) {                    // 3 t per chunk
                __align__(16) __half2 h[12];
                #pragma unroll
                for (int tt = 0; tt < 3; tt++) {
                    int t = tc * 3 + tt;
                    const float4* xp = (const float4*)(x + ((size_t)t * NN + n) * 16);
                    float4 a = xp[0], bq = xp[1], c = xp[2], d = xp[3];
                    h[tt * 4 + 0] = __floats2half2_rn(a.x * ds, a.y * ds);
                    h[tt * 4 + 1] = __floats2half2_rn(a.z * ds, a.w * ds);
                    h[tt * 4 + 2] = __floats2half2_rn(bq.x * ds, bq.y * ds);
                    h[tt * 4 + 3] = __floats2half2_rn(bq.z * ds, bq.w * ds);
                    // second half of the 16 channels
                    h[tt * 4 + 0] = h[tt * 4 + 0];  // keep layout explicit below
                    // note: 16 ch = 8 half2; pack remaining 4 half2:
                    // reuse local temps to fill h[..] correctly:
                    // (handled explicitly right below)
                    h[tt * 4 + 2] = __floats2half2_rn(b ? 0.f : 0.f, 0.f); // placeholder overwritten
                    (void)c; (void)d;
                    // Correct packing (overwrite placeholders):
                    h[tt * 4 + 0] = __floats2half2_rn(a.x * ds, a.y * ds);
                    h[tt * 4 + 1] = __floats2half2_rn(a.z * ds, a.w * ds);
                    h[tt * 4 + 2] = __floats2half2_rn(bq.x * ds, bq.y * ds);
                    h[tt * 4 + 3] = __floats2half2_rn(bq.z * ds, bq.w * ds);
                    // c,d hold channels 8..15 -> second uint4 of this t
                    // stored via a second local array:
                    // to keep arrays simple, we write both uint4 now:
                    uint4 u0 = *(const uint4*)&h[tt * 4];
                    __align__(16) __half2 h2[4];
                    h2[0] = __floats2half2_rn(c.x * ds, c.y * ds);
                    h2[1] = __floats2half2_rn(c.z * ds, c.w * ds);
                    h2[2] = __floats2half2_rn(d.x * ds, d.y * ds);
                    h2[3] = __floats2half2_rn(d.z * ds, d.w * ds);
                    uint4 u1 = *(const uint4*)h2;
                    dst[t * 2 + 0] = u0;
                    dst[t * 2 + 1] = u1;
                }
            }
        }
    }
}

// ================= K4 (PROFILED): aggregation (warp per dst, fp16 in/out) =============
__global__ void k_agg() {
    const int lane = threadIdx.x & 31, wid = threadIdx.x >> 5;
    const int dst = blockIdx.x * 8 + wid;              // 12500*8 == NN
    const int e0 = g_off[dst], e1 = g_off[dst + 1];
    float2 a0 = {0.f, 0.f}, a1 = {0.f, 0.f}, a2 = {0.f, 0.f};
    float2 b0 = {0.f, 0.f}, b1 = {0.f, 0.f}, b2 = {0.f, 0.f};
    const unsigned int* xb = (const unsigned int*)g_xsh;   // half2 units, 96/node
    int e = e0;
    for (; e + 1 < e1; e += 2) {
        float2 ed0 = g_edge[e];
        float2 ed1 = g_edge[e + 1];
        int   s0 = __float_as_int(ed0.x), s1 = __float_as_int(ed1.x);
        float w0 = ed0.y,                 w1 = ed1.y;
        const unsigned int* p0 = xb + (size_t)s0 * 96 + lane;
        const unsigned int* p1 = xb + (size_t)s1 * 96 + lane;
        unsigned int u00 = p0[0], u01 = p0[32], u02 = p0[64];
        unsigned int u10 = p1[0], u11 = p1[32], u12 = p1[64];
        float2 v;
        v = __half22float2(*(const __half2*)&u00);
        a0.x = fmaf(w0, v.x, a0.x); a0.y = fmaf(w0, v.y, a0.y);
        v = __half22float2(*(const __half2*)&u01);
        a1.x = fmaf(w0, v.x, a1.x); a1.y = fmaf(w0, v.y, a1.y);
        v = __half22float2(*(const __half2*)&u02);
        a2.x = fmaf(w0, v.x, a2.x); a2.y = fmaf(w0, v.y, a2.y);
        v = __half22float2(*(const __half2*)&u10);
        b0.x = fmaf(w1, v.x, b0.x); b0.y = fmaf(w1, v.y, b0.y);
        v = __half22float2(*(const __half2*)&u11);
        b1.x = fmaf(w1, v.x, b1.x); b1.y = fmaf(w1, v.y, b1.y);
        v = __half22float2(*(const __half2*)&u12);
        b2.x = fmaf(w1, v.x, b2.x); b2.y = fmaf(w1, v.y, b2.y);
    }
    if (e < e1) {
        float2 ed = g_edge[e];
        int   s = __float_as_int(ed.x);
        float w = ed.y;
        const unsigned int* p = xb + (size_t)s * 96 + lane;
        unsigned int u0 = p[0], u1 = p[32], u2 = p[64];
        float2 v;
        v = __half22float2(*(const __half2*)&u0);
        a0.x = fmaf(w, v.x, a0.x); a0.y = fmaf(w, v.y, a0.y);
        v = __half22float2(*(const __half2*)&u1);
        a1.x = fmaf(w, v.x, a1.x); a1.y = fmaf(w, v.y, a1.y);
        v = __half22float2(*(const __half2*)&u2);
        a2.x = fmaf(w, v.x, a2.x); a2.y = fmaf(w, v.y, a2.y);
    }
    a0.x += b0.x; a0.y += b0.y;
    a1.x += b1.x; a1.y += b1.y;
    a2.x += b2.x; a2.y += b2.y;
    __half2* q = g_axh + (size_t)dst * 96 + lane;
    q[0]  = __floats2half2_rn(a0.x, a0.y);
    q[32] = __floats2half2_rn(a1.x, a1.y);
    q[64] = __floats2half2_rn(a2.x, a2.y);
}

// ================= K5: weight fuse + bias (tiny) ======================================
#define NB_F 72
#define NB_B 2
__global__ void k_fuseB(const float* __restrict__ gw, const float* __restrict__ cw,
                        const float* __restrict__ gb, const float* __restrict__ cb) {
    const int b = blockIdx.x, tid = threadIdx.x;
    if (b < NB_F) {
        int f = b * 256 + tid;
        int co = f & 31, ci = (f >> 5) & 15, tk = f >> 9;
        int t = tk / 3, k = tk % 3;
        float acc = 0.f;
        #pragma unroll
        for (int cm = 0; cm < CMID; cm++)
            acc = fmaf(gw[(t * CI_N + ci) * CMID + cm], cw[(co * CMID + cm) * 3 + k], acc);
        g_M[((t * 3 + k) * CI_N + ci) * COUT + co] = acc;
    } else {
        int g = (b - NB_F) * 256 + tid;
        if (g < TW * COUT) {
            int co = g & 31, w = g >> 5;
            float acc = cb[co];
            #pragma unroll
            for (int k = 0; k < 3; k++) {
                int t = w + k - 1;
                if (t >= 0 && t < TW)
                    #pragma unroll
                    for (int cm = 0; cm < CMID; cm++)
                        acc = fmaf(gb[t * CMID + cm], cw[(co * CMID + cm) * 3 + k], acc);
            }
            g_B[w * COUT + co] = acc;
        }
    }
}

// ================= K6: output GEMM, all 12 w fused (proven inner loop, fp16 X in) =====
#define OB_NODES 128
#define OB_PAIRS 64
#define XSTR 193                                    // float2 row stride (bank-skew pad)
#define OSM (OB_PAIRS * XSTR * 8 + 576 * 32 * 4 + TW * 32 * 4)   // 174 KB
__global__ __launch_bounds__(512, 1)
void k_out(float* __restrict__ out) {
    extern __shared__ __align__(16) float sm[];
    float2* Xp = (float2*)sm;                       // [64][193] float2 (node pairs)
    float*  Ms = sm + OB_PAIRS * XSTR * 2;          // [576][32]
    float*  Bs = Ms + 576 * 32;                     // [384]
    const int tid = threadIdx.x;
    const int n0  = blockIdx.x * OB_NODES;

    for (int u = tid; u < 576 * 32; u += 512) Ms[u] = g_M[u];
    if (tid < TW * 32) Bs[tid] = g_B[tid];
    for (int u = tid; u < OB_PAIRS * 24; u += 512) {
        int p = u / 24, j = u - p * 24;
        int na = n0 + 2 * p, nb = na + 1;
        uint4 ua = make_uint4(0u, 0u, 0u, 0u), ub = ua;
        const uint4* base = (const uint4*)g_axh;
        if (na < NN) ua = base[(size_t)na * 24 + j];
        if (nb < NN) ub = base[(size_t)nb * 24 + j];
        float2* row = Xp + p * XSTR + 8 * j;
        float2 a, b;
        a = __half22float2(*(const __half2*)&ua.x); b = __half22float2(*(const __half2*)&ub.x);
        row[0] = make_float2(a.x, b.x); row[1] = make_float2(a.y, b.y);
        a = __half22float2(*(const __half2*)&ua.y); b = __half22float2(*(const __half2*)&ub.y);
        row[2] = make_float2(a.x, b.x); row[3] = make_float2(a.y, b.y);
        a = __half22float2(*(const __half2*)&ua.z); b = __half22float2(*(const __half2*)&ub.z);
        row[4] = make_float2(a.x, b.x); row[5] = make_float2(a.y, b.y);
        a = __half22float2(*(const __half2*)&ua.w); b = __half22float2(*(const __half2*)&ub.w);
        row[6] = make_float2(a.x, b.x); row[7] = make_float2(a.y, b.y);
    }
    __syncthreads();

    const int cg = tid & 7;                 // 8 co-groups of 4
    const int p  = tid >> 3;                // 64 pairs
    const unsigned long long* xrow = (const unsigned long long*)(Xp + p * XSTR);
    const int na = n0 + 2 * p, nb = na + 1;

    #pragma unroll
    for (int h = 0; h < 2; h++) {           // w halves [0,6) and [6,12)
        unsigned long long acc[6][4];
        #pragma unroll
        for (int wl = 0; wl < 6; wl++)
            #pragma unroll
            for (int c = 0; c < 4; c++) acc[wl][c] = 0ull;

        const int tbase = h ? 5 : 0;
        #pragma unroll
        for (int dt = 0; dt < 7; dt++) {
            const int t = tbase + dt;
            #pragma unroll
            for (int ci = 0; ci < CI_N; ci++) {
                unsigned long long xv = xrow[t * 16 + ci];
                #pragma unroll
                for (int k = 0; k < 3; k++) {
                    const int w = t + 1 - k;
                    if (w >= h * 6 && w < h * 6 + 6) {
                        const int wl = w - h * 6;
                        float4 m = *(const float4*)(Ms + ((t * 3 + k) * 16 + ci) * 32 + cg * 4);
                        acc[wl][0] = fma2(xv, pk2(m.x, m.x), acc[wl][0]);
                        acc[wl][1] = fma2(xv, pk2(m.y, m.y), acc[wl][1]);
                        acc[wl][2] = fma2(xv, pk2(m.z, m.z), acc[wl][2]);
                        acc[wl][3] = fma2(xv, pk2(m.w, m.w), acc[wl][3]);
                    }
                }
            }
        }
        #pragma unroll
        for (int wl = 0; wl < 6; wl++) {
            const int w = h * 6 + wl;
            float o0[4], o1[4];
            #pragma unroll
            for (int c = 0; c < 4; c++) {
                float lo, hi;
                upk2(lo, hi, acc[wl][c]);
                float bv = Bs[w * 32 + cg * 4 + c];
                lo += bv; hi += bv;
                o0[c] = lo >= 0.f ? lo : 0.01f * lo;
                o1[c] = hi >= 0.f ? hi : 0.01f * hi;
            }
            if (na < NN)
                *(float4*)(out + (size_t)na * (TW * COUT) + w * COUT + cg * 4)
                    = make_float4(o0[0], o0[1], o0[2], o0[3]);
            if (nb < NN)
                *(float4*)(out + (size_t)nb * (TW * COUT) + w * COUT + cg * 4)
                    = make_float4(o1[0], o1[1], o1[2], o1[3]);
        }
    }
}

extern "C" void kernel_launch(void* const* d_in, const int* in_sizes, int n_in,
                              void* d_out, int out_size) {
    const float* x  = (const float*)d_in[0];   // [W,N,16]
    const int*   A  = (const int*)  d_in[1];   // [2,E]
    const float* ew = (const float*)d_in[2];   // [E]
    const float* gw = (const float*)d_in[3];   // [W,16,32]
    const float* gb = (const float*)d_in[4];   // [W,32]
    const float* cw = (const float*)d_in[5];   // [32,32,3]
    const float* cb = (const float*)d_in[6];   // [32]
    float* out = (float*)d_out;                // [N,W,32]

    cudaFuncSetAttribute(k_out, cudaFuncAttributeMaxDynamicSharedMemorySize, OSM);

    void* p_zb;
    cudaGetSymbolAddress(&p_zb, g_zb);
    cudaMemsetAsync(p_zb, 0, sizeof(ZBlob));

    k_megaE<<<EE / 512, 256>>>(A, ew);                          // kernel 1
    k_scan <<<NSCAN, 1024>>>();                                 // kernel 2
    k_scatX<<<NB_S + NB_T, 256>>>(A, ew, x);                    // kernel 3
    k_agg  <<<NN / 8, 256>>>();                                 // kernel 4 -> ncu
    k_fuseB<<<NB_F + NB_B, 256>>>(gw, cw, gb, cb);              // kernel 5
    k_out  <<<dim3((NN + OB_NODES - 1) / OB_NODES, 1), 512, OSM>>>(out);  // kernel 6
}

// round 16
// speedup vs baseline: 1.0383x; 1.0383x over previous
#include <cuda_runtime.h>
#include <cuda_fp16.h>

#define NN   100000
#define EE   1600000
#define TW   12
#define CI_N 16
#define CMID 32
#define COUT 32

#define NSCAN 98                      // ceil(NN/1024)

// ---- scratch (allocation-free rule: __device__ globals) ----
struct ZBlob {                         // zeroed by ONE memset per launch
    unsigned long long pk[NN];         // (cnt << 32) | fixed-point(deg, 2^-24)
    unsigned long long stat[NSCAN];    // decoupled-lookback state
};
__device__ ZBlob   g_zb;
__device__ float   g_dis[NN];
__device__ int     g_off[NN + 1];
__device__ int     g_cur[NN];
__device__ float2  g_edge[EE];                        // (src as int bits, ew*dis[dst])
__device__ __half  g_xsh[(size_t)NN * TW * CI_N];     // dis[n]*x, node-major fp16
__device__ __half2 g_axh[(size_t)NN * 96];            // aggregated x, fp16 (38.4 MB)
__device__ float   g_M  [TW * 3 * CI_N * COUT];       // fused gcn_w @ conv_w
__device__ float   g_B  [TW * COUT];                  // fused bias

// ---- packed f32x2 helpers (Blackwell FFMA2) ----
__device__ __forceinline__ unsigned long long pk2(float lo, float hi) {
    unsigned long long r;
    asm("mov.b64 %0, {%1, %2};" : "=l"(r) : "f"(lo), "f"(hi));
    return r;
}
__device__ __forceinline__ void upk2(float& lo, float& hi, unsigned long long v) {
    asm("mov.b64 {%0, %1}, %2;" : "=f"(lo), "=f"(hi) : "l"(v));
}
__device__ __forceinline__ unsigned long long fma2(unsigned long long a,
                                                   unsigned long long b,
                                                   unsigned long long c) {
    unsigned long long d;
    asm("fma.rn.f32x2 %0, %1, %2, %3;" : "=l"(d) : "l"(a), "l"(b), "l"(c));
    return d;
}

// ================= K1: edge histogram — ONE packed 64-bit RED per edge ================
__global__ void k_megaE(const int* __restrict__ A, const float* __restrict__ ew) {
    int e2 = (blockIdx.x * 256 + threadIdx.x) * 2;     // 3125*256*2 == EE exactly
    int2   c2 = *(const int2*)(A + EE + e2);
    float2 w2 = *(const float2*)(ew + e2);
    unsigned long long p0 = (1ull << 32) | (unsigned)__float2uint_rn(w2.x * 16777216.f);
    unsigned long long p1 = (1ull << 32) | (unsigned)__float2uint_rn(w2.y * 16777216.f);
    atomicAdd(&g_zb.pk[c2.x], p0);
    atomicAdd(&g_zb.pk[c2.y], p1);
}

// ================= K2: single-pass exclusive scan + dis = rsqrt(deg) ==================
__global__ __launch_bounds__(1024) void k_scan() {
    __shared__ int wsum[33];
    __shared__ int s_prefix;
    const int tid = threadIdx.x, lane = tid & 31, wid = tid >> 5, bid = blockIdx.x;
    const int i = bid * 1024 + tid;
    unsigned long long pki = (i < NN) ? g_zb.pk[i] : 0ull;
    int v = (int)(pki >> 32);
    int incl = v;
    #pragma unroll
    for (int d = 1; d < 32; d <<= 1) {
        int t = __shfl_up_sync(0xffffffffu, incl, d);
        if (lane >= d) incl += t;
    }
    if (lane == 31) wsum[wid] = incl;
    __syncthreads();
    if (wid == 0) {
        int x  = wsum[lane];
        int ix = x;
        #pragma unroll
        for (int d = 1; d < 32; d <<= 1) {
            int t = __shfl_up_sync(0xffffffffu, ix, d);
            if (lane >= d) ix += t;
        }
        wsum[lane] = ix - x;
        if (lane == 31) wsum[32] = ix;
    }
    __syncthreads();
    const int excl  = wsum[wid] + incl - v;
    const int total = wsum[32];

    if (tid == 0) {
        unsigned long long pk = ((unsigned long long)(bid == 0 ? 2u : 1u) << 32)
                              | (unsigned)total;
        atomicExch(&g_zb.stat[bid], pk);
        if (bid == 0) s_prefix = 0;
    }
    if (bid != 0 && wid == 0) {
        volatile unsigned long long* vs = g_zb.stat;
        int pred = bid - 1;
        int run = 0;
        for (;;) {
            int idx = pred - lane;
            unsigned long long st;
            if (idx >= 0) {
                do { st = vs[idx]; } while ((unsigned)(st >> 32) == 0u);
            } else {
                st = (2ull << 32);
            }
            unsigned flag = (unsigned)(st >> 32);
            int      val  = (int)(unsigned)st;
            unsigned mask = __ballot_sync(0xffffffffu, flag == 2u);
            if (mask) {
                int L = __ffs(mask) - 1;
                int contrib = (lane <= L) ? val : 0;
                #pragma unroll
                for (int d = 16; d >= 1; d >>= 1)
                    contrib += __shfl_xor_sync(0xffffffffu, contrib, d);
                run += contrib;
                break;
            } else {
                int contrib = val;
                #pragma unroll
                for (int d = 16; d >= 1; d >>= 1)
                    contrib += __shfl_xor_sync(0xffffffffu, contrib, d);
                run += contrib;
                pred -= 32;
            }
        }
        if (lane == 0) {
            s_prefix = run;
            atomicExch(&g_zb.stat[bid], (2ull << 32) | (unsigned)(run + total));
        }
    }
    __syncthreads();
    const int pre = s_prefix;
    if (i < NN) {
        int o = excl + pre;
        g_off[i] = o;
        g_cur[i] = o;
        float deg = (float)(unsigned)(pki & 0xffffffffull) * (1.f / 16777216.f);
        g_dis[i] = deg > 0.f ? rsqrtf(deg) : 0.f;
    }
    if (bid == NSCAN - 1 && tid == 0) g_off[NN] = EE;
}

// ================= K3: scatter into CSR — norm = ew*dis[dst] ==========================
__global__ void k_scatter(const int* __restrict__ A, const float* __restrict__ ew) {
    int e2 = (blockIdx.x * 256 + threadIdx.x) * 2;     // 3125*256*2 == EE exactly
    int2   r2 = *(const int2*)(A + e2);
    int2   c2 = *(const int2*)(A + EE + e2);
    float2 w2 = *(const float2*)(ew + e2);
    float n0 = w2.x * g_dis[c2.x];
    float n1 = w2.y * g_dis[c2.y];
    int i0 = atomicAdd(&g_cur[c2.x], 1);
    g_edge[i0] = make_float2(__int_as_float(r2.x), n0);
    int i1 = atomicAdd(&g_cur[c2.y], 1);
    g_edge[i1] = make_float2(__int_as_float(r2.y), n1);
}

// ================= K4 (PROFILED): megaT — NODE-MAJOR dis-scaled transpose | fuse | bias
#define NB_X 391                       // ceil(NN/256), one thread per node
#define NB_F 72
#define NB_B 2
__global__ void k_megaT(const float* __restrict__ x, const float* __restrict__ gw,
                        const float* __restrict__ cw, const float* __restrict__ gb,
                        const float* __restrict__ cb) {
    const int b = blockIdx.x, tid = threadIdx.x;
    if (b < NB_X) {
        // node-major: thread = node. 12 independent 64B coalesced read streams,
        // one contiguous 384B write per node (warp stores 12KB contiguous).
        int n = b * 256 + tid;
        if (n < NN) {
            float ds = g_dis[n];
            uint4* dst = (uint4*)(g_xsh + (size_t)n * 192);
            #pragma unroll
            for (int t = 0; t < TW; t++) {
                const float4* xp = (const float4*)(x + ((size_t)t * NN + n) * 16);
                float4 a = xp[0], bq = xp[1], c = xp[2], d = xp[3];
                __align__(16) __half2 h[8];
                h[0] = __floats2half2_rn(a.x * ds,  a.y * ds);
                h[1] = __floats2half2_rn(a.z * ds,  a.w * ds);
                h[2] = __floats2half2_rn(bq.x * ds, bq.y * ds);
                h[3] = __floats2half2_rn(bq.z * ds, bq.w * ds);
                h[4] = __floats2half2_rn(c.x * ds,  c.y * ds);
                h[5] = __floats2half2_rn(c.z * ds,  c.w * ds);
                h[6] = __floats2half2_rn(d.x * ds,  d.y * ds);
                h[7] = __floats2half2_rn(d.z * ds,  d.w * ds);
                const uint4* src = (const uint4*)h;
                dst[t * 2 + 0] = src[0];
                dst[t * 2 + 1] = src[1];
            }
        }
    } else if (b < NB_X + NB_F) {
        int f = (b - NB_X) * 256 + tid;
        int co = f & 31, ci = (f >> 5) & 15, tk = f >> 9;
        int t = tk / 3, k = tk % 3;
        float acc = 0.f;
        #pragma unroll
        for (int cm = 0; cm < CMID; cm++)
            acc = fmaf(gw[(t * CI_N + ci) * CMID + cm], cw[(co * CMID + cm) * 3 + k], acc);
        g_M[((t * 3 + k) * CI_N + ci) * COUT + co] = acc;
    } else {
        int g = (b - NB_X - NB_F) * 256 + tid;
        if (g < TW * COUT) {
            int co = g & 31, w = g >> 5;
            float acc = cb[co];
            #pragma unroll
            for (int k = 0; k < 3; k++) {
                int t = w + k - 1;
                if (t >= 0 && t < TW)
                    #pragma unroll
                    for (int cm = 0; cm < CMID; cm++)
                        acc = fmaf(gb[t * CMID + cm], cw[(co * CMID + cm) * 3 + k], acc);
            }
            g_B[w * COUT + co] = acc;
        }
    }
}

// ================= K5: aggregation (warp per dst, 2-edge unroll, fp16 in/out) =========
__global__ void k_agg() {
    const int lane = threadIdx.x & 31, wid = threadIdx.x >> 5;
    const int dst = blockIdx.x * 8 + wid;              // 12500*8 == NN
    const int e0 = g_off[dst], e1 = g_off[dst + 1];
    float2 a0 = {0.f, 0.f}, a1 = {0.f, 0.f}, a2 = {0.f, 0.f};
    float2 b0 = {0.f, 0.f}, b1 = {0.f, 0.f}, b2 = {0.f, 0.f};
    const unsigned int* xb = (const unsigned int*)g_xsh;   // half2 units, 96/node
    int e = e0;
    for (; e + 1 < e1; e += 2) {
        float2 ed0 = g_edge[e];
        float2 ed1 = g_edge[e + 1];
        int   s0 = __float_as_int(ed0.x), s1 = __float_as_int(ed1.x);
        float w0 = ed0.y,                 w1 = ed1.y;
        const unsigned int* p0 = xb + (size_t)s0 * 96 + lane;
        const unsigned int* p1 = xb + (size_t)s1 * 96 + lane;
        unsigned int u00 = p0[0], u01 = p0[32], u02 = p0[64];
        unsigned int u10 = p1[0], u11 = p1[32], u12 = p1[64];
        float2 v;
        v = __half22float2(*(const __half2*)&u00);
        a0.x = fmaf(w0, v.x, a0.x); a0.y = fmaf(w0, v.y, a0.y);
        v = __half22float2(*(const __half2*)&u01);
        a1.x = fmaf(w0, v.x, a1.x); a1.y = fmaf(w0, v.y, a1.y);
        v = __half22float2(*(const __half2*)&u02);
        a2.x = fmaf(w0, v.x, a2.x); a2.y = fmaf(w0, v.y, a2.y);
        v = __half22float2(*(const __half2*)&u10);
        b0.x = fmaf(w1, v.x, b0.x); b0.y = fmaf(w1, v.y, b0.y);
        v = __half22float2(*(const __half2*)&u11);
        b1.x = fmaf(w1, v.x, b1.x); b1.y = fmaf(w1, v.y, b1.y);
        v = __half22float2(*(const __half2*)&u12);
        b2.x = fmaf(w1, v.x, b2.x); b2.y = fmaf(w1, v.y, b2.y);
    }
    if (e < e1) {
        float2 ed = g_edge[e];
        int   s = __float_as_int(ed.x);
        float w = ed.y;
        const unsigned int* p = xb + (size_t)s * 96 + lane;
        unsigned int u0 = p[0], u1 = p[32], u2 = p[64];
        float2 v;
        v = __half22float2(*(const __half2*)&u0);
        a0.x = fmaf(w, v.x, a0.x); a0.y = fmaf(w, v.y, a0.y);
        v = __half22float2(*(const __half2*)&u1);
        a1.x = fmaf(w, v.x, a1.x); a1.y = fmaf(w, v.y, a1.y);
        v = __half22float2(*(const __half2*)&u2);
        a2.x = fmaf(w, v.x, a2.x); a2.y = fmaf(w, v.y, a2.y);
    }
    a0.x += b0.x; a0.y += b0.y;
    a1.x += b1.x; a1.y += b1.y;
    a2.x += b2.x; a2.y += b2.y;
    __half2* q = g_axh + (size_t)dst * 96 + lane;
    q[0]  = __floats2half2_rn(a0.x, a0.y);
    q[32] = __floats2half2_rn(a1.x, a1.y);
    q[64] = __floats2half2_rn(a2.x, a2.y);
}

// ================= K6: output GEMM, all 12 w fused (proven inner loop, fp16 X in) =====
#define OB_NODES 128
#define OB_PAIRS 64
#define XSTR 193                                    // float2 row stride (bank-skew pad)
#define OSM (OB_PAIRS * XSTR * 8 + 576 * 32 * 4 + TW * 32 * 4)   // 174 KB
__global__ __launch_bounds__(512, 1)
void k_out(float* __restrict__ out) {
    extern __shared__ __align__(16) float sm[];
    float2* Xp = (float2*)sm;                       // [64][193] float2 (node pairs)
    float*  Ms = sm + OB_PAIRS * XSTR * 2;          // [576][32]
    float*  Bs = Ms + 576 * 32;                     // [384]
    const int tid = threadIdx.x;
    const int n0  = blockIdx.x * OB_NODES;

    for (int u = tid; u < 576 * 32; u += 512) Ms[u] = g_M[u];
    if (tid < TW * 32) Bs[tid] = g_B[tid];
    for (int u = tid; u < OB_PAIRS * 24; u += 512) {
        int p = u / 24, j = u - p * 24;
        int na = n0 + 2 * p, nb = na + 1;
        uint4 ua = make_uint4(0u, 0u, 0u, 0u), ub = ua;
        const uint4* base = (const uint4*)g_axh;
        if (na < NN) ua = base[(size_t)na * 24 + j];
        if (nb < NN) ub = base[(size_t)nb * 24 + j];
        float2* row = Xp + p * XSTR + 8 * j;
        float2 a, b;
        a = __half22float2(*(const __half2*)&ua.x); b = __half22float2(*(const __half2*)&ub.x);
        row[0] = make_float2(a.x, b.x); row[1] = make_float2(a.y, b.y);
        a = __half22float2(*(const __half2*)&ua.y); b = __half22float2(*(const __half2*)&ub.y);
        row[2] = make_float2(a.x, b.x); row[3] = make_float2(a.y, b.y);
        a = __half22float2(*(const __half2*)&ua.z); b = __half22float2(*(const __half2*)&ub.z);
        row[4] = make_float2(a.x, b.x); row[5] = make_float2(a.y, b.y);
        a = __half22float2(*(const __half2*)&ua.w); b = __half22float2(*(const __half2*)&ub.w);
        row[6] = make_float2(a.x, b.x); row[7] = make_float2(a.y, b.y);
    }
    __syncthreads();

    const int cg = tid & 7;                 // 8 co-groups of 4
    const int p  = tid >> 3;                // 64 pairs
    const unsigned long long* xrow = (const unsigned long long*)(Xp + p * XSTR);
    const int na = n0 + 2 * p, nb = na + 1;

    #pragma unroll
    for (int h = 0; h < 2; h++) {           // w halves [0,6) and [6,12)
        unsigned long long acc[6][4];
        #pragma unroll
        for (int wl = 0; wl < 6; wl++)
            #pragma unroll
            for (int c = 0; c < 4; c++) acc[wl][c] = 0ull;

        const int tbase = h ? 5 : 0;
        #pragma unroll
        for (int dt = 0; dt < 7; dt++) {
            const int t = tbase + dt;
            #pragma unroll
            for (int ci = 0; ci < CI_N; ci++) {
                unsigned long long xv = xrow[t * 16 + ci];
                #pragma unroll
                for (int k = 0; k < 3; k++) {
                    const int w = t + 1 - k;
                    if (w >= h * 6 && w < h * 6 + 6) {
                        const int wl = w - h * 6;
                        float4 m = *(const float4*)(Ms + ((t * 3 + k) * 16 + ci) * 32 + cg * 4);
                        acc[wl][0] = fma2(xv, pk2(m.x, m.x), acc[wl][0]);
                        acc[wl][1] = fma2(xv, pk2(m.y, m.y), acc[wl][1]);
                        acc[wl][2] = fma2(xv, pk2(m.z, m.z), acc[wl][2]);
                        acc[wl][3] = fma2(xv, pk2(m.w, m.w), acc[wl][3]);
                    }
                }
            }
        }
        #pragma unroll
        for (int wl = 0; wl < 6; wl++) {
            const int w = h * 6 + wl;
            float o0[4], o1[4];
            #pragma unroll
            for (int c = 0; c < 4; c++) {
                float lo, hi;
                upk2(lo, hi, acc[wl][c]);
                float bv = Bs[w * 32 + cg * 4 + c];
                lo += bv; hi += bv;
                o0[c] = lo >= 0.f ? lo : 0.01f * lo;
                o1[c] = hi >= 0.f ? hi : 0.01f * hi;
            }
            if (na < NN)
                *(float4*)(out + (size_t)na * (TW * COUT) + w * COUT + cg * 4)
                    = make_float4(o0[0], o0[1], o0[2], o0[3]);
            if (nb < NN)
                *(float4*)(out + (size_t)nb * (TW * COUT) + w * COUT + cg * 4)
                    = make_float4(o1[0], o1[1], o1[2], o1[3]);
        }
    }
}

extern "C" void kernel_launch(void* const* d_in, const int* in_sizes, int n_in,
                              void* d_out, int out_size) {
    const float* x  = (const float*)d_in[0];   // [W,N,16]
    const int*   A  = (const int*)  d_in[1];   // [2,E]
    const float* ew = (const float*)d_in[2];   // [E]
    const float* gw = (const float*)d_in[3];   // [W,16,32]
    const float* gb = (const float*)d_in[4];   // [W,32]
    const float* cw = (const float*)d_in[5];   // [32,32,3]
    const float* cb = (const float*)d_in[6];   // [32]
    float* out = (float*)d_out;                // [N,W,32]

    cudaFuncSetAttribute(k_out, cudaFuncAttributeMaxDynamicSharedMemorySize, OSM);

    void* p_zb;
    cudaGetSymbolAddress(&p_zb, g_zb);
    cudaMemsetAsync(p_zb, 0, sizeof(ZBlob));

    k_megaE  <<<EE / 512, 256>>>(A, ew);                       // kernel 1
    k_scan   <<<NSCAN, 1024>>>();                              // kernel 2
    k_scatter<<<EE / 512, 256>>>(A, ew);                       // kernel 3
    k_megaT  <<<NB_X + NB_F + NB_B, 256>>>(x, gw, cw, gb, cb); // kernel 4 -> ncu
    k_agg    <<<NN / 8, 256>>>();                              // kernel 5
    k_out    <<<dim3((NN + OB_NODES - 1) / OB_NODES, 1), 512, OSM>>>(out);  // kernel 6
}

// round 17
// speedup vs baseline: 1.0695x; 1.0300x over previous
#include <cuda_runtime.h>
#include <cuda_fp16.h>

#define NN   100000
#define EE   1600000
#define TW   12
#define CI_N 16
#define CMID 32
#define COUT 32

#define NSCAN 98                      // ceil(NN/1024)

// ---- scratch (allocation-free rule: __device__ globals) ----
struct ZBlob {                         // zeroed by ONE memset per launch
    unsigned long long pk[NN];         // (cnt << 32) | fixed-point(deg, 2^-24)
    unsigned long long stat[NSCAN];    // decoupled-lookback state
};
__device__ ZBlob   g_zb;
__device__ float   g_dis[NN];
__device__ int     g_off[NN + 1];
__device__ int     g_cur[NN];
__device__ float2  g_edge[EE];                        // (src as int bits, ew*dis[dst])
__device__ __half  g_xsh[(size_t)NN * TW * CI_N];     // dis[n]*x, node-major fp16
__device__ __half2 g_axh[(size_t)NN * 96];            // aggregated x, fp16 (38.4 MB)
__device__ float   g_M  [TW * 3 * CI_N * COUT];       // fused gcn_w @ conv_w
__device__ float   g_B  [TW * COUT];                  // fused bias

// ---- packed f32x2 helpers (Blackwell FFMA2) ----
__device__ __forceinline__ unsigned long long pk2(float lo, float hi) {
    unsigned long long r;
    asm("mov.b64 %0, {%1, %2};" : "=l"(r) : "f"(lo), "f"(hi));
    return r;
}
__device__ __forceinline__ void upk2(float& lo, float& hi, unsigned long long v) {
    asm("mov.b64 {%0, %1}, %2;" : "=f"(lo), "=f"(hi) : "l"(v));
}
__device__ __forceinline__ unsigned long long fma2(unsigned long long a,
                                                   unsigned long long b,
                                                   unsigned long long c) {
    unsigned long long d;
    asm("fma.rn.f32x2 %0, %1, %2, %3;" : "=l"(d) : "l"(a), "l"(b), "l"(c));
    return d;
}

// ================= K1: edge histogram — ONE packed 64-bit RED per edge ================
__global__ void k_megaE(const int* __restrict__ A, const float* __restrict__ ew) {
    int e2 = (blockIdx.x * 256 + threadIdx.x) * 2;     // 3125*256*2 == EE exactly
    int2   c2 = *(const int2*)(A + EE + e2);
    float2 w2 = *(const float2*)(ew + e2);
    unsigned long long p0 = (1ull << 32) | (unsigned)__float2uint_rn(w2.x * 16777216.f);
    unsigned long long p1 = (1ull << 32) | (unsigned)__float2uint_rn(w2.y * 16777216.f);
    atomicAdd(&g_zb.pk[c2.x], p0);
    atomicAdd(&g_zb.pk[c2.y], p1);
}

// ================= K2: single-pass exclusive scan + dis = rsqrt(deg) ==================
__global__ __launch_bounds__(1024) void k_scan() {
    __shared__ int wsum[33];
    __shared__ int s_prefix;
    const int tid = threadIdx.x, lane = tid & 31, wid = tid >> 5, bid = blockIdx.x;
    const int i = bid * 1024 + tid;
    unsigned long long pki = (i < NN) ? g_zb.pk[i] : 0ull;
    int v = (int)(pki >> 32);
    int incl = v;
    #pragma unroll
    for (int d = 1; d < 32; d <<= 1) {
        int t = __shfl_up_sync(0xffffffffu, incl, d);
        if (lane >= d) incl += t;
    }
    if (lane == 31) wsum[wid] = incl;
    __syncthreads();
    if (wid == 0) {
        int x  = wsum[lane];
        int ix = x;
        #pragma unroll
        for (int d = 1; d < 32; d <<= 1) {
            int t = __shfl_up_sync(0xffffffffu, ix, d);
            if (lane >= d) ix += t;
        }
        wsum[lane] = ix - x;
        if (lane == 31) wsum[32] = ix;
    }
    __syncthreads();
    const int excl  = wsum[wid] + incl - v;
    const int total = wsum[32];

    if (tid == 0) {
        unsigned long long pk = ((unsigned long long)(bid == 0 ? 2u : 1u) << 32)
                              | (unsigned)total;
        atomicExch(&g_zb.stat[bid], pk);
        if (bid == 0) s_prefix = 0;
    }
    if (bid != 0 && wid == 0) {
        volatile unsigned long long* vs = g_zb.stat;
        int pred = bid - 1;
        int run = 0;
        for (;;) {
            int idx = pred - lane;
            unsigned long long st;
            if (idx >= 0) {
                do { st = vs[idx]; } while ((unsigned)(st >> 32) == 0u);
            } else {
                st = (2ull << 32);
            }
            unsigned flag = (unsigned)(st >> 32);
            int      val  = (int)(unsigned)st;
            unsigned mask = __ballot_sync(0xffffffffu, flag == 2u);
            if (mask) {
                int L = __ffs(mask) - 1;
                int contrib = (lane <= L) ? val : 0;
                #pragma unroll
                for (int d = 16; d >= 1; d >>= 1)
                    contrib += __shfl_xor_sync(0xffffffffu, contrib, d);
                run += contrib;
                break;
            } else {
                int contrib = val;
                #pragma unroll
                for (int d = 16; d >= 1; d >>= 1)
                    contrib += __shfl_xor_sync(0xffffffffu, contrib, d);
                run += contrib;
                pred -= 32;
            }
        }
        if (lane == 0) {
            s_prefix = run;
            atomicExch(&g_zb.stat[bid], (2ull << 32) | (unsigned)(run + total));
        }
    }
    __syncthreads();
    const int pre = s_prefix;
    if (i < NN) {
        int o = excl + pre;
        g_off[i] = o;
        g_cur[i] = o;
        float deg = (float)(unsigned)(pki & 0xffffffffull) * (1.f / 16777216.f);
        g_dis[i] = deg > 0.f ? rsqrtf(deg) : 0.f;
    }
    if (bid == NSCAN - 1 && tid == 0) g_off[NN] = EE;
}

// ================= K3: scatter into CSR — norm = ew*dis[dst] ==========================
__global__ void k_scatter(const int* __restrict__ A, const float* __restrict__ ew) {
    int e2 = (blockIdx.x * 256 + threadIdx.x) * 2;     // 3125*256*2 == EE exactly
    int2   r2 = *(const int2*)(A + e2);
    int2   c2 = *(const int2*)(A + EE + e2);
    float2 w2 = *(const float2*)(ew + e2);
    float n0 = w2.x * g_dis[c2.x];
    float n1 = w2.y * g_dis[c2.y];
    int i0 = atomicAdd(&g_cur[c2.x], 1);
    g_edge[i0] = make_float2(__int_as_float(r2.x), n0);
    int i1 = atomicAdd(&g_cur[c2.y], 1);
    g_edge[i1] = make_float2(__int_as_float(r2.y), n1);
}

// ================= K4 (PROFILED): megaT — SMEM-TILED transpose | fuse | bias ==========
// Transpose tile: 64 nodes/block. Load: coalesced reads (per t: 256 threads cover
// 64 nodes x 16ch contiguous), all 12 t in flight. Stage in padded smem.
// Write: contiguous 384B/node rows (warp stores ~2KB contiguous).
#define TNODES 64
#define TSTRIDE 104                    // uints per node in smem (pad: 104 % 32 = 8)
#define NB_X 1563                      // ceil(NN/64)
#define NB_F 72
#define NB_B 2
__global__ void k_megaT(const float* __restrict__ x, const float* __restrict__ gw,
                        const float* __restrict__ cw, const float* __restrict__ gb,
                        const float* __restrict__ cb) {
    __shared__ unsigned int smt[TNODES * TSTRIDE];     // 26.6 KB
    const int b = blockIdx.x, tid = threadIdx.x;
    if (b < NB_X) {
        const int n0 = b * TNODES;
        const int nl = tid >> 2;                       // node-local 0..63 (fixed/thread)
        const int q  = tid & 3;                        // float4 index within 16 ch
        const int n  = n0 + nl;
        const bool ok = (n < NN);
        float ds = ok ? g_dis[n] : 0.f;

        // load all 12 t (independent, coalesced), convert, stage in smem
        float4 v[TW];
        #pragma unroll
        for (int t = 0; t < TW; t++)
            v[t] = ok ? *(const float4*)(x + ((size_t)t * NN + n) * 16 + q * 4)
                      : make_float4(0.f, 0.f, 0.f, 0.f);
        #pragma unroll
        for (int t = 0; t < TW; t++) {
            __half2 h0 = __floats2half2_rn(v[t].x * ds, v[t].y * ds);
            __half2 h1 = __floats2half2_rn(v[t].z * ds, v[t].w * ds);
            smt[nl * TSTRIDE + t * 8 + q * 2 + 0] = *(const unsigned int*)&h0;
            smt[nl * TSTRIDE + t * 8 + q * 2 + 1] = *(const unsigned int*)&h1;
        }
        __syncthreads();

        // write phase: 64 nodes x 24 uint4 = 1536 uint4; 6 per thread, coalesced out
        #pragma unroll
        for (int i = 0; i < 6; i++) {
            int u  = i * 256 + tid;
            int wn = u / 24, j = u - wn * 24;
            int gn = n0 + wn;
            if (gn < NN) {
                uint4 val = *(const uint4*)&smt[wn * TSTRIDE + j * 4];
                ((uint4*)(g_xsh + (size_t)gn * 192))[j] = val;
            }
        }
    } else if (b < NB_X + NB_F) {
        int f = (b - NB_X) * 256 + tid;
        int co = f & 31, ci = (f >> 5) & 15, tk = f >> 9;
        int t = tk / 3, k = tk % 3;
        float acc = 0.f;
        #pragma unroll
        for (int cm = 0; cm < CMID; cm++)
            acc = fmaf(gw[(t * CI_N + ci) * CMID + cm], cw[(co * CMID + cm) * 3 + k], acc);
        g_M[((t * 3 + k) * CI_N + ci) * COUT + co] = acc;
    } else {
        int g = (b - NB_X - NB_F) * 256 + tid;
        if (g < TW * COUT) {
            int co = g & 31, w = g >> 5;
            float acc = cb[co];
            #pragma unroll
            for (int k = 0; k < 3; k++) {
                int t = w + k - 1;
                if (t >= 0 && t < TW)
                    #pragma unroll
                    for (int cm = 0; cm < CMID; cm++)
                        acc = fmaf(gb[t * CMID + cm], cw[(co * CMID + cm) * 3 + k], acc);
            }
            g_B[w * COUT + co] = acc;
        }
    }
}

// ================= K5: aggregation (warp per dst, 2-edge unroll, fp16 in/out) =========
__global__ void k_agg() {
    const int lane = threadIdx.x & 31, wid = threadIdx.x >> 5;
    const int dst = blockIdx.x * 8 + wid;              // 12500*8 == NN
    const int e0 = g_off[dst], e1 = g_off[dst + 1];
    float2 a0 = {0.f, 0.f}, a1 = {0.f, 0.f}, a2 = {0.f, 0.f};
    float2 b0 = {0.f, 0.f}, b1 = {0.f, 0.f}, b2 = {0.f, 0.f};
    const unsigned int* xb = (const unsigned int*)g_xsh;   // half2 units, 96/node
    int e = e0;
    for (; e + 1 < e1; e += 2) {
        float2 ed0 = g_edge[e];
        float2 ed1 = g_edge[e + 1];
        int   s0 = __float_as_int(ed0.x), s1 = __float_as_int(ed1.x);
        float w0 = ed0.y,                 w1 = ed1.y;
        const unsigned int* p0 = xb + (size_t)s0 * 96 + lane;
        const unsigned int* p1 = xb + (size_t)s1 * 96 + lane;
        unsigned int u00 = p0[0], u01 = p0[32], u02 = p0[64];
        unsigned int u10 = p1[0], u11 = p1[32], u12 = p1[64];
        float2 v;
        v = __half22float2(*(const __half2*)&u00);
        a0.x = fmaf(w0, v.x, a0.x); a0.y = fmaf(w0, v.y, a0.y);
        v = __half22float2(*(const __half2*)&u01);
        a1.x = fmaf(w0, v.x, a1.x); a1.y = fmaf(w0, v.y, a1.y);
        v = __half22float2(*(const __half2*)&u02);
        a2.x = fmaf(w0, v.x, a2.x); a2.y = fmaf(w0, v.y, a2.y);
        v = __half22float2(*(const __half2*)&u10);
        b0.x = fmaf(w1, v.x, b0.x); b0.y = fmaf(w1, v.y, b0.y);
        v = __half22float2(*(const __half2*)&u11);
        b1.x = fmaf(w1, v.x, b1.x); b1.y = fmaf(w1, v.y, b1.y);
        v = __half22float2(*(const __half2*)&u12);
        b2.x = fmaf(w1, v.x, b2.x); b2.y = fmaf(w1, v.y, b2.y);
    }
    if (e < e1) {
        float2 ed = g_edge[e];
        int   s = __float_as_int(ed.x);
        float w = ed.y;
        const unsigned int* p = xb + (size_t)s * 96 + lane;
        unsigned int u0 = p[0], u1 = p[32], u2 = p[64];
        float2 v;
        v = __half22float2(*(const __half2*)&u0);
        a0.x = fmaf(w, v.x, a0.x); a0.y = fmaf(w, v.y, a0.y);
        v = __half22float2(*(const __half2*)&u1);
        a1.x = fmaf(w, v.x, a1.x); a1.y = fmaf(w, v.y, a1.y);
        v = __half22float2(*(const __half2*)&u2);
        a2.x = fmaf(w, v.x, a2.x); a2.y = fmaf(w, v.y, a2.y);
    }
    a0.x += b0.x; a0.y += b0.y;
    a1.x += b1.x; a1.y += b1.y;
    a2.x += b2.x; a2.y += b2.y;
    __half2* q = g_axh + (size_t)dst * 96 + lane;
    q[0]  = __floats2half2_rn(a0.x, a0.y);
    q[32] = __floats2half2_rn(a1.x, a1.y);
    q[64] = __floats2half2_rn(a2.x, a2.y);
}

// ================= K6: output GEMM, all 12 w fused (proven inner loop, fp16 X in) =====
#define OB_NODES 128
#define OB_PAIRS 64
#define XSTR 193                                    // float2 row stride (bank-skew pad)
#define OSM (OB_PAIRS * XSTR * 8 + 576 * 32 * 4 + TW * 32 * 4)   // 174 KB
__global__ __launch_bounds__(512, 1)
void k_out(float* __restrict__ out) {
    extern __shared__ __align__(16) float sm[];
    float2* Xp = (float2*)sm;                       // [64][193] float2 (node pairs)
    float*  Ms = sm + OB_PAIRS * XSTR * 2;          // [576][32]
    float*  Bs = Ms + 576 * 32;                     // [384]
    const int tid = threadIdx.x;
    const int n0  = blockIdx.x * OB_NODES;

    for (int u = tid; u < 576 * 32; u += 512) Ms[u] = g_M[u];
    if (tid < TW * 32) Bs[tid] = g_B[tid];
    for (int u = tid; u < OB_PAIRS * 24; u += 512) {
        int p = u / 24, j = u - p * 24;
        int na = n0 + 2 * p, nb = na + 1;
        uint4 ua = make_uint4(0u, 0u, 0u, 0u), ub = ua;
        const uint4* base = (const uint4*)g_axh;
        if (na < NN) ua = base[(size_t)na * 24 + j];
        if (nb < NN) ub = base[(size_t)nb * 24 + j];
        float2* row = Xp + p * XSTR + 8 * j;
        float2 a, b;
        a = __half22float2(*(const __half2*)&ua.x); b = __half22float2(*(const __half2*)&ub.x);
        row[0] = make_float2(a.x, b.x); row[1] = make_float2(a.y, b.y);
        a = __half22float2(*(const __half2*)&ua.y); b = __half22float2(*(const __half2*)&ub.y);
        row[2] = make_float2(a.x, b.x); row[3] = make_float2(a.y, b.y);
        a = __half22float2(*(const __half2*)&ua.z); b = __half22float2(*(const __half2*)&ub.z);
        row[4] = make_float2(a.x, b.x); row[5] = make_float2(a.y, b.y);
        a = __half22float2(*(const __half2*)&ua.w); b = __half22float2(*(const __half2*)&ub.w);
        row[6] = make_float2(a.x, b.x); row[7] = make_float2(a.y, b.y);
    }
    __syncthreads();

    const int cg = tid & 7;                 // 8 co-groups of 4
    const int p  = tid >> 3;                // 64 pairs
    const unsigned long long* xrow = (const unsigned long long*)(Xp + p * XSTR);
    const int na = n0 + 2 * p, nb = na + 1;

    #pragma unroll
    for (int h = 0; h < 2; h++) {           // w halves [0,6) and [6,12)
        unsigned long long acc[6][4];
        #pragma unroll
        for (int wl = 0; wl < 6; wl++)
            #pragma unroll
            for (int c = 0; c < 4; c++) acc[wl][c] = 0ull;

        const int tbase = h ? 5 : 0;
        #pragma unroll
        for (int dt = 0; dt < 7; dt++) {
            const int t = tbase + dt;
            #pragma unroll
            for (int ci = 0; ci < CI_N; ci++) {
                unsigned long long xv = xrow[t * 16 + ci];
                #pragma unroll
                for (int k = 0; k < 3; k++) {
                    const int w = t + 1 - k;
                    if (w >= h * 6 && w < h * 6 + 6) {
                        const int wl = w - h * 6;
                        float4 m = *(const float4*)(Ms + ((t * 3 + k) * 16 + ci) * 32 + cg * 4);
                        acc[wl][0] = fma2(xv, pk2(m.x, m.x), acc[wl][0]);
                        acc[wl][1] = fma2(xv, pk2(m.y, m.y), acc[wl][1]);
                        acc[wl][2] = fma2(xv, pk2(m.z, m.z), acc[wl][2]);
                        acc[wl][3] = fma2(xv, pk2(m.w, m.w), acc[wl][3]);
                    }
                }
            }
        }
        #pragma unroll
        for (int wl = 0; wl < 6; wl++) {
            const int w = h * 6 + wl;
            float o0[4], o1[4];
            #pragma unroll
            for (int c = 0; c < 4; c++) {
                float lo, hi;
                upk2(lo, hi, acc[wl][c]);
                float bv = Bs[w * 32 + cg * 4 + c];
                lo += bv; hi += bv;
                o0[c] = lo >= 0.f ? lo : 0.01f * lo;
                o1[c] = hi >= 0.f ? hi : 0.01f * hi;
            }
            if (na < NN)
                *(float4*)(out + (size_t)na * (TW * COUT) + w * COUT + cg * 4)
                    = make_float4(o0[0], o0[1], o0[2], o0[3]);
            if (nb < NN)
                *(float4*)(out + (size_t)nb * (TW * COUT) + w * COUT + cg * 4)
                    = make_float4(o1[0], o1[1], o1[2], o1[3]);
        }
    }
}

extern "C" void kernel_launch(void* const* d_in, const int* in_sizes, int n_in,
                              void* d_out, int out_size) {
    const float* x  = (const float*)d_in[0];   // [W,N,16]
    const int*   A  = (const int*)  d_in[1];   // [2,E]
    const float* ew = (const float*)d_in[2];   // [E]
    const float* gw = (const float*)d_in[3];   // [W,16,32]
    const float* gb = (const float*)d_in[4];   // [W,32]
    const float* cw = (const float*)d_in[5];   // [32,32,3]
    const float* cb = (const float*)d_in[6];   // [32]
    float* out = (float*)d_out;                // [N,W,32]

    cudaFuncSetAttribute(k_out, cudaFuncAttributeMaxDynamicSharedMemorySize, OSM);

    void* p_zb;
    cudaGetSymbolAddress(&p_zb, g_zb);
    cudaMemsetAsync(p_zb, 0, sizeof(ZBlob));

    k_megaE  <<<EE / 512, 256>>>(A, ew);                       // kernel 1
    k_scan   <<<NSCAN, 1024>>>();                              // kernel 2
    k_scatter<<<EE / 512, 256>>>(A, ew);                       // kernel 3
    k_megaT  <<<NB_X + NB_F + NB_B, 256>>>(x, gw, cw, gb, cb); // kernel 4 -> ncu
    k_agg    <<<NN / 8, 256>>>();                              // kernel 5
    k_out    <<<dim3((NN + OB_NODES - 1) / OB_NODES, 1), 512, OSM>>>(out);  // kernel 6
}